// round 1
// baseline (speedup 1.0000x reference)
#include <cuda_runtime.h>
#include <math.h>

// ---------------------------------------------------------------------------
// Problem constants (batch already halved: cat(x,x) duplicates, out[:b] keeps half)
//   B=32, C=512, N=256 (seq), H=8, P=256 (patch flat), HC=4096
// ---------------------------------------------------------------------------

// Scratch (device globals; no cudaMalloc allowed)
__device__ float g_emb[32 * 256 * 512];      //  (b, n, c)
__device__ float g_xn [32 * 256 * 512];      //  LN outputs (reused for LN2 output)
__device__ float g_q  [32 * 256 * 4096];     //  (b, n, h*512+i); reused for ctx2
__device__ float g_k  [32 * 256 * 4096];
__device__ float g_v  [32 * 256 * 4096];
__device__ float g_sc [32 * 8 * 512 * 512];  //  scores -> attn in place
__device__ float g_ob [32 * 256 * 512];      //  out-proj + residual
__device__ float g_st [32 * 8 * 2];          //  instance-norm mean/rstd
__device__ float g_wqT[4096 * 512];
__device__ float g_wkT[4096 * 512];
__device__ float g_wvT[4096 * 512];
__device__ float g_woT[512 * 4096];          //  woT[o,h*512+c] = wo[c*8+h, o]

__device__ __forceinline__ float gelu_f(float x) {
    return 0.5f * x * (1.0f + erff(x * 0.70710678118654752f));
}

// ---------------------------------------------------------------------------
// Epilogue shared by both GEMM variants.
// EPI: 0 none | 1 +bias[m] | 2 +res[m*ldc+n] | 3 +bias[m] then exact GELU
// ---------------------------------------------------------------------------
template <int EPI>
__device__ __forceinline__ void epi_store(float acc[4][4], float* Cb, int ldc,
                                          int m0, int n0, int tx, int ty,
                                          const float* __restrict__ epp) {
#pragma unroll
    for (int i = 0; i < 4; ++i) {
        const int m = m0 + (ty << 2) + i;
        float4 r = make_float4(acc[i][0], acc[i][1], acc[i][2], acc[i][3]);
        if (EPI == 1 || EPI == 3) {
            const float bi = epp[m];
            r.x += bi; r.y += bi; r.z += bi; r.w += bi;
        }
        if (EPI == 2) {
            const float4 rv = *reinterpret_cast<const float4*>(epp + (long)m * ldc + n0 + (tx << 2));
            r.x += rv.x; r.y += rv.y; r.z += rv.z; r.w += rv.w;
        }
        if (EPI == 3) {
            r.x = gelu_f(r.x); r.y = gelu_f(r.y); r.z = gelu_f(r.z); r.w = gelu_f(r.w);
        }
        *reinterpret_cast<float4*>(Cb + (long)m * ldc + n0 + (tx << 2)) = r;
    }
}

// ---------------------------------------------------------------------------
// NT GEMM: C[m,n] = sum_k A[m,k]*B[n,k], A/B row-major K-contiguous.
// 64x64 tile, BK=32, 256 threads, 4x4 per thread. M,N multiples of 64; K of 32.
// Batched: z = b*Hdiv + h; per-operand (b,h) strides.
// ---------------------------------------------------------------------------
template <int EPI>
__global__ void __launch_bounds__(256) gemm_nt(
    const float* __restrict__ A, int lda, long sAb, long sAh,
    const float* __restrict__ B, int ldb, long sBb, long sBh,
    float* __restrict__ C, int ldc, long sCb, long sCh,
    int K, int Hdiv, const float* __restrict__ ep, long sEpb) {
    __shared__ float As[32][68];
    __shared__ float Bs[32][68];
    const int z = blockIdx.z;
    const int b = z / Hdiv, h = z - b * Hdiv;
    const float* Ab = A + (long)b * sAb + (long)h * sAh;
    const float* Bb = B + (long)b * sBb + (long)h * sBh;
    float* Cb = C + (long)b * sCb + (long)h * sCh;
    const float* epp = ep ? (ep + (long)b * sEpb) : ep;

    const int m0 = blockIdx.y << 6;
    const int n0 = blockIdx.x << 6;
    const int tid = threadIdx.x;
    const int tx = tid & 15, ty = tid >> 4;
    const int lr = tid >> 3;           // 0..31 (row within 64-tile, two passes)
    const int lc = (tid & 7) << 2;     // 0..28 (k offset, float4)

    float acc[4][4] = {};
    for (int k0 = 0; k0 < K; k0 += 32) {
#pragma unroll
        for (int p = 0; p < 2; ++p) {
            const float4 av = *reinterpret_cast<const float4*>(Ab + (long)(m0 + lr + p * 32) * lda + k0 + lc);
            As[lc + 0][lr + p * 32] = av.x; As[lc + 1][lr + p * 32] = av.y;
            As[lc + 2][lr + p * 32] = av.z; As[lc + 3][lr + p * 32] = av.w;
            const float4 bv = *reinterpret_cast<const float4*>(Bb + (long)(n0 + lr + p * 32) * ldb + k0 + lc);
            Bs[lc + 0][lr + p * 32] = bv.x; Bs[lc + 1][lr + p * 32] = bv.y;
            Bs[lc + 2][lr + p * 32] = bv.z; Bs[lc + 3][lr + p * 32] = bv.w;
        }
        __syncthreads();
#pragma unroll
        for (int kk = 0; kk < 32; ++kk) {
            const float4 a4 = *reinterpret_cast<const float4*>(&As[kk][ty << 2]);
            const float4 b4 = *reinterpret_cast<const float4*>(&Bs[kk][tx << 2]);
            const float a[4] = {a4.x, a4.y, a4.z, a4.w};
            const float bb[4] = {b4.x, b4.y, b4.z, b4.w};
#pragma unroll
            for (int i = 0; i < 4; ++i)
#pragma unroll
                for (int j = 0; j < 4; ++j) acc[i][j] = fmaf(a[i], bb[j], acc[i][j]);
        }
        __syncthreads();
    }
    epi_store<EPI>(acc, Cb, ldc, m0, n0, tx, ty, epp);
}

// ---------------------------------------------------------------------------
// TN GEMM: C[m,n] = sum_k A[k*lda+m]*B[k*ldb+n]  (operands M/N-contiguous).
// Used for scores = Q^T K with Q,K stored (n, h*512+i).
// ---------------------------------------------------------------------------
template <int EPI>
__global__ void __launch_bounds__(256) gemm_tn(
    const float* __restrict__ A, int lda, long sAb, long sAh,
    const float* __restrict__ B, int ldb, long sBb, long sBh,
    float* __restrict__ C, int ldc, long sCb, long sCh,
    int K, int Hdiv, const float* __restrict__ ep, long sEpb) {
    __shared__ float As[32][68];
    __shared__ float Bs[32][68];
    const int z = blockIdx.z;
    const int b = z / Hdiv, h = z - b * Hdiv;
    const float* Ab = A + (long)b * sAb + (long)h * sAh;
    const float* Bb = B + (long)b * sBb + (long)h * sBh;
    float* Cb = C + (long)b * sCb + (long)h * sCh;
    const float* epp = ep ? (ep + (long)b * sEpb) : ep;

    const int m0 = blockIdx.y << 6;
    const int n0 = blockIdx.x << 6;
    const int tid = threadIdx.x;
    const int tx = tid & 15, ty = tid >> 4;
    const int kr = tid >> 4;           // 0..15 (two passes -> 32 k rows)
    const int mc = (tid & 15) << 2;    // 0..60 (float4 along M/N)

    float acc[4][4] = {};
    for (int k0 = 0; k0 < K; k0 += 32) {
#pragma unroll
        for (int p = 0; p < 2; ++p) {
            const float4 av = *reinterpret_cast<const float4*>(Ab + (long)(k0 + kr + p * 16) * lda + m0 + mc);
            *reinterpret_cast<float4*>(&As[kr + p * 16][mc]) = av;
            const float4 bv = *reinterpret_cast<const float4*>(Bb + (long)(k0 + kr + p * 16) * ldb + n0 + mc);
            *reinterpret_cast<float4*>(&Bs[kr + p * 16][mc]) = bv;
        }
        __syncthreads();
#pragma unroll
        for (int kk = 0; kk < 32; ++kk) {
            const float4 a4 = *reinterpret_cast<const float4*>(&As[kk][ty << 2]);
            const float4 b4 = *reinterpret_cast<const float4*>(&Bs[kk][tx << 2]);
            const float a[4] = {a4.x, a4.y, a4.z, a4.w};
            const float bb[4] = {b4.x, b4.y, b4.z, b4.w};
#pragma unroll
            for (int i = 0; i < 4; ++i)
#pragma unroll
                for (int j = 0; j < 4; ++j) acc[i][j] = fmaf(a[i], bb[j], acc[i][j]);
        }
        __syncthreads();
    }
    epi_store<EPI>(acc, Cb, ldc, m0, n0, tx, ty, epp);
}

// ---------------------------------------------------------------------------
// LayerNorm over last dim (512). One warp per row, float4 vectorized.
// ---------------------------------------------------------------------------
__global__ void __launch_bounds__(256) ln_kernel(
    const float* __restrict__ in, float* __restrict__ out,
    const float* __restrict__ gamma, const float* __restrict__ beta, float eps) {
    const int warp = blockIdx.x * (blockDim.x >> 5) + (threadIdx.x >> 5);
    const int lane = threadIdx.x & 31;
    const float4* r = reinterpret_cast<const float4*>(in + (long)warp * 512);
    float4 v[4];
    float s = 0.f, s2 = 0.f;
#pragma unroll
    for (int i = 0; i < 4; ++i) {
        v[i] = r[lane + (i << 5)];
        s  += v[i].x + v[i].y + v[i].z + v[i].w;
        s2 += v[i].x * v[i].x + v[i].y * v[i].y + v[i].z * v[i].z + v[i].w * v[i].w;
    }
#pragma unroll
    for (int o = 16; o > 0; o >>= 1) {
        s  += __shfl_xor_sync(0xffffffffu, s, o);
        s2 += __shfl_xor_sync(0xffffffffu, s2, o);
    }
    const float mu = s * (1.f / 512.f);
    const float rstd = rsqrtf(s2 * (1.f / 512.f) - mu * mu + eps);
    float4* w = reinterpret_cast<float4*>(out + (long)warp * 512);
#pragma unroll
    for (int i = 0; i < 4; ++i) {
        const float4 g4 = reinterpret_cast<const float4*>(gamma)[lane + (i << 5)];
        const float4 b4 = reinterpret_cast<const float4*>(beta)[lane + (i << 5)];
        float4 o4;
        o4.x = (v[i].x - mu) * rstd * g4.x + b4.x;
        o4.y = (v[i].y - mu) * rstd * g4.y + b4.y;
        o4.z = (v[i].z - mu) * rstd * g4.z + b4.z;
        o4.w = (v[i].w - mu) * rstd * g4.w + b4.w;
        w[lane + (i << 5)] = o4;
    }
}

// ---------------------------------------------------------------------------
// InstanceNorm stats: per (b,h), mean/rstd over 512x512.
// ---------------------------------------------------------------------------
__global__ void __launch_bounds__(256) inorm_stats(const float* __restrict__ sc,
                                                   float* __restrict__ stats) {
    __shared__ float sh[256], sh2[256];
    const int z = blockIdx.x;
    const float4* p = reinterpret_cast<const float4*>(sc + (long)z * 262144);
    float s = 0.f, s2 = 0.f;
    for (int i = threadIdx.x; i < 65536; i += 256) {
        const float4 v = p[i];
        s  += v.x + v.y + v.z + v.w;
        s2 += v.x * v.x + v.y * v.y + v.z * v.z + v.w * v.w;
    }
    sh[threadIdx.x] = s; sh2[threadIdx.x] = s2;
    __syncthreads();
    for (int o = 128; o > 0; o >>= 1) {
        if (threadIdx.x < o) { sh[threadIdx.x] += sh[threadIdx.x + o]; sh2[threadIdx.x] += sh2[threadIdx.x + o]; }
        __syncthreads();
    }
    if (threadIdx.x == 0) {
        const float mu = sh[0] * (1.f / 262144.f);
        const float var = sh2[0] * (1.f / 262144.f) - mu * mu;
        stats[z * 2 + 0] = mu;
        stats[z * 2 + 1] = rsqrtf(var + 1e-5f);
    }
}

// ---------------------------------------------------------------------------
// Fused instance-norm-apply + softmax over rows of 512, in place. One warp/row.
// ---------------------------------------------------------------------------
__global__ void __launch_bounds__(256) softmax_rows(float* __restrict__ sc,
                                                    const float* __restrict__ stats) {
    const int warp = blockIdx.x * (blockDim.x >> 5) + (threadIdx.x >> 5);
    const int lane = threadIdx.x & 31;
    const int z = warp >> 9;
    const float mu = stats[z * 2 + 0];
    const float rstd = stats[z * 2 + 1];
    float4* row = reinterpret_cast<float4*>(sc + (long)warp * 512);
    float4 v[4];
    float mx = -1e30f;
#pragma unroll
    for (int i = 0; i < 4; ++i) {
        v[i] = row[lane + (i << 5)];
        v[i].x = (v[i].x - mu) * rstd; v[i].y = (v[i].y - mu) * rstd;
        v[i].z = (v[i].z - mu) * rstd; v[i].w = (v[i].w - mu) * rstd;
        mx = fmaxf(mx, fmaxf(fmaxf(v[i].x, v[i].y), fmaxf(v[i].z, v[i].w)));
    }
#pragma unroll
    for (int o = 16; o > 0; o >>= 1) mx = fmaxf(mx, __shfl_xor_sync(0xffffffffu, mx, o));
    float s = 0.f;
#pragma unroll
    for (int i = 0; i < 4; ++i) {
        v[i].x = __expf(v[i].x - mx); v[i].y = __expf(v[i].y - mx);
        v[i].z = __expf(v[i].z - mx); v[i].w = __expf(v[i].w - mx);
        s += v[i].x + v[i].y + v[i].z + v[i].w;
    }
#pragma unroll
    for (int o = 16; o > 0; o >>= 1) s += __shfl_xor_sync(0xffffffffu, s, o);
    const float inv = 1.f / s;
#pragma unroll
    for (int i = 0; i < 4; ++i) {
        v[i].x *= inv; v[i].y *= inv; v[i].z *= inv; v[i].w *= inv;
        row[lane + (i << 5)] = v[i];
    }
}

// ---------------------------------------------------------------------------
// Weight pre-processing
// ---------------------------------------------------------------------------
__global__ void __launch_bounds__(256) transpose_rc(const float* __restrict__ in,
                                                    float* __restrict__ out,
                                                    int rows, int cols) {
    // out[c*rows + r] = in[r*cols + c]
    __shared__ float t[32][33];
    const int c0 = blockIdx.x << 5, r0 = blockIdx.y << 5;
    const int tx = threadIdx.x, ty = threadIdx.y;  // 32 x 8
#pragma unroll
    for (int j = 0; j < 32; j += 8) t[ty + j][tx] = in[(long)(r0 + ty + j) * cols + c0 + tx];
    __syncthreads();
#pragma unroll
    for (int j = 0; j < 32; j += 8) out[(long)(c0 + ty + j) * rows + r0 + tx] = t[tx][ty + j];
}

__global__ void __launch_bounds__(256) permute_wo(const float* __restrict__ wo,
                                                  float* __restrict__ woT) {
    // woT[o*4096 + h*512 + c] = wo[(c*8+h)*512 + o]
    const long idx = (long)blockIdx.x * 256 + threadIdx.x;  // over 512*4096
    const int o = (int)(idx & 511);
    const int ch = (int)(idx >> 9);
    const int h = ch & 7;
    const int c = ch >> 3;
    woT[(long)o * 4096 + h * 512 + c] = wo[idx];
}

// ---------------------------------------------------------------------------
// Host launcher
// ---------------------------------------------------------------------------
extern "C" void kernel_launch(void* const* d_in, const int* in_sizes, int n_in,
                              void* d_out, int out_size) {
    const float* x      = (const float*)d_in[0];
    const float* proj_w = (const float*)d_in[1];
    const float* proj_b = (const float*)d_in[2];
    const float* ln1_g  = (const float*)d_in[3];
    const float* ln1_b  = (const float*)d_in[4];
    const float* wq     = (const float*)d_in[5];
    const float* wk     = (const float*)d_in[6];
    const float* wv     = (const float*)d_in[7];
    const float* wo     = (const float*)d_in[8];
    const float* ln2_g  = (const float*)d_in[9];
    const float* ln2_b  = (const float*)d_in[10];
    const float* mo_w   = (const float*)d_in[11];
    const float* mo_b   = (const float*)d_in[12];
    float* out = (float*)d_out;

    float *emb, *xn, *q, *k, *v, *sc, *ob, *st, *wqT, *wkT, *wvT, *woT;
    cudaGetSymbolAddress((void**)&emb, g_emb);
    cudaGetSymbolAddress((void**)&xn,  g_xn);
    cudaGetSymbolAddress((void**)&q,   g_q);
    cudaGetSymbolAddress((void**)&k,   g_k);
    cudaGetSymbolAddress((void**)&v,   g_v);
    cudaGetSymbolAddress((void**)&sc,  g_sc);
    cudaGetSymbolAddress((void**)&ob,  g_ob);
    cudaGetSymbolAddress((void**)&st,  g_st);
    cudaGetSymbolAddress((void**)&wqT, g_wqT);
    cudaGetSymbolAddress((void**)&wkT, g_wkT);
    cudaGetSymbolAddress((void**)&wvT, g_wvT);
    cudaGetSymbolAddress((void**)&woT, g_woT);

    // Weight prep
    transpose_rc<<<dim3(128, 16), dim3(32, 8)>>>(wq, wqT, 512, 4096);
    transpose_rc<<<dim3(128, 16), dim3(32, 8)>>>(wk, wkT, 512, 4096);
    transpose_rc<<<dim3(128, 16), dim3(32, 8)>>>(wv, wvT, 512, 4096);
    permute_wo<<<8192, 256>>>(wo, woT);

    // 1) Patch embed: emb[b,n,c] = sum_p proj_w[n,p]*x[b,c,p] + proj_b[n]
    gemm_nt<1><<<dim3(8, 4, 32), 256>>>(proj_w, 256, 0, 0,
                                        x, 256, 131072L, 0,
                                        emb, 512, 131072L, 0,
                                        256, 1, proj_b, 0);
    // 2) LN1
    ln_kernel<<<1024, 256>>>(emb, xn, ln1_g, ln1_b, 1e-6f);
    // 3) Q,K,V: (b) [256x512] @ [512x4096]  (NT vs pre-transposed weights)
    gemm_nt<0><<<dim3(64, 4, 32), 256>>>(xn, 512, 131072L, 0, wqT, 512, 0, 0,
                                         q, 4096, 1048576L, 0, 512, 1, nullptr, 0);
    gemm_nt<0><<<dim3(64, 4, 32), 256>>>(xn, 512, 131072L, 0, wkT, 512, 0, 0,
                                         k, 4096, 1048576L, 0, 512, 1, nullptr, 0);
    gemm_nt<0><<<dim3(64, 4, 32), 256>>>(xn, 512, 131072L, 0, wvT, 512, 0, 0,
                                         v, 4096, 1048576L, 0, 512, 1, nullptr, 0);
    // 4) Scores: per (b,h) [512x512] = Q^T K over n=256  (TN)
    gemm_tn<0><<<dim3(8, 8, 256), 256>>>(q, 4096, 1048576L, 512, k, 4096, 1048576L, 512,
                                         sc, 512, 2097152L, 262144L, 256, 8, nullptr, 0);
    // 5) InstanceNorm stats + fused normalize+softmax (in place)
    inorm_stats<<<256, 256>>>(sc, st);
    softmax_rows<<<16384, 256>>>(sc, st);
    // 6) ctx2[b,n,h,i] = sum_j v[b,n,h,j]*attn[b,h,i,j]  (NT, writes over g_q)
    gemm_nt<0><<<dim3(8, 4, 256), 256>>>(v, 4096, 1048576L, 512, sc, 512, 2097152L, 262144L,
                                         q, 4096, 1048576L, 512, 512, 8, nullptr, 0);
    // 7) Out-proj + residual: [256x4096] @ woT^T + emb
    gemm_nt<2><<<dim3(8, 4, 32), 256>>>(q, 4096, 1048576L, 0, woT, 4096, 0, 0,
                                        ob, 512, 131072L, 0, 4096, 1, emb, 131072L);
    // 8) LN2 (reuse g_xn)
    ln_kernel<<<1024, 256>>>(ob, xn, ln2_g, ln2_b, 1e-6f);
    // 9) 1x1 conv + bias + exact GELU, direct to d_out in (b,o,p) layout
    gemm_nt<3><<<dim3(4, 8, 32), 256>>>(mo_w, 512, 0, 0, xn, 512, 131072L, 0,
                                        out, 256, 131072L, 0, 512, 1, mo_b, 0);
}